// round 2
// baseline (speedup 1.0000x reference)
#include <cuda_runtime.h>
#include <cstdint>

// APPNP: h <- 0.9 * A@h + 0.1 * x, 10 iterations, A given as edge list.
// Strategy: build CSR (grouped by destination row) once per launch, then run
// atomic-free warp-per-row SpMM 10x with register accumulators. Gathers of
// h[col] (25.6MB working set) hit L2.

#define N_NODES 100000
#define N_EDGES 3200000
#define D_FEAT  64
#define ALPHA   0.1f
#define K_STEPS 10

// -------- static device scratch (no allocations allowed) --------
__device__ int   g_count[N_NODES];
__device__ int   g_fill[N_NODES];
__device__ int   g_rowptr[N_NODES + 1];
__device__ int2  g_cw[N_EDGES];                     // {col, bits(weight)}
__device__ float g_h[2][(size_t)N_NODES * D_FEAT];  // ping-pong h buffers

// -------- CSR build --------
__global__ void k_zero_counts() {
    int i = blockIdx.x * blockDim.x + threadIdx.x;
    if (i < N_NODES) { g_count[i] = 0; g_fill[i] = 0; }
}

__global__ void k_hist(const int* __restrict__ erow) {
    int e = blockIdx.x * blockDim.x + threadIdx.x;
    if (e < N_EDGES) atomicAdd(&g_count[erow[e]], 1);
}

// single-block exclusive scan over g_count -> g_rowptr (n = N_NODES)
__global__ void k_scan() {
    __shared__ int sdata[1024];
    __shared__ int carry;
    if (threadIdx.x == 0) carry = 0;
    __syncthreads();
    for (int base = 0; base < N_NODES; base += 1024) {
        int i = base + threadIdx.x;
        int v = (i < N_NODES) ? g_count[i] : 0;
        sdata[threadIdx.x] = v;
        __syncthreads();
        // inclusive scan in shared
        for (int off = 1; off < 1024; off <<= 1) {
            int t = (threadIdx.x >= off) ? sdata[threadIdx.x - off] : 0;
            __syncthreads();
            sdata[threadIdx.x] += t;
            __syncthreads();
        }
        int incl = sdata[threadIdx.x];
        if (i < N_NODES) g_rowptr[i] = carry + incl - v;  // exclusive
        __syncthreads();
        if (threadIdx.x == 1023) carry += sdata[1023];
        __syncthreads();
    }
    if (threadIdx.x == 0) g_rowptr[N_NODES] = carry;
}

__global__ void k_scatter(const int* __restrict__ erow,
                          const int* __restrict__ ecol,
                          const float* __restrict__ ew) {
    int e = blockIdx.x * blockDim.x + threadIdx.x;
    if (e < N_EDGES) {
        int r = erow[e];
        int p = g_rowptr[r] + atomicAdd(&g_fill[r], 1);
        g_cw[p] = make_int2(ecol[e], __float_as_int(ew[e]));
    }
}

// -------- SpMM: one warp per row, float2 per lane (32 lanes * 2 = 64 feats) --------
__global__ void __launch_bounds__(256)
k_spmm(const float* __restrict__ src, const float* __restrict__ x,
       float* __restrict__ dst) {
    int warp = (blockIdx.x * blockDim.x + threadIdx.x) >> 5;
    int lane = threadIdx.x & 31;
    if (warp >= N_NODES) return;

    int beg = g_rowptr[warp];
    int end = g_rowptr[warp + 1];

    float accx = 0.0f, accy = 0.0f;

    for (int base = beg; base < end; base += 32) {
        int e = base + lane;
        int2 cw = (e < end) ? g_cw[e] : make_int2(0, 0);
        int m = end - base; if (m > 32) m = 32;
        #pragma unroll 4
        for (int j = 0; j < m; j++) {
            int   c  = __shfl_sync(0xffffffffu, cw.x, j);
            float wv = __int_as_float(__shfl_sync(0xffffffffu, cw.y, j));
            float2 hv = *(const float2*)(src + (size_t)c * D_FEAT + lane * 2);
            accx = fmaf(wv, hv.x, accx);
            accy = fmaf(wv, hv.y, accy);
        }
    }

    float2 xv = *(const float2*)(x + (size_t)warp * D_FEAT + lane * 2);
    float2 out;
    out.x = fmaf(1.0f - ALPHA, accx, ALPHA * xv.x);
    out.y = fmaf(1.0f - ALPHA, accy, ALPHA * xv.y);
    *(float2*)(dst + (size_t)warp * D_FEAT + lane * 2) = out;
}

extern "C" void kernel_launch(void* const* d_in, const int* in_sizes, int n_in,
                              void* d_out, int out_size) {
    const float* x    = (const float*)d_in[0];
    const int*   erow = (const int*)d_in[1];
    const int*   ecol = (const int*)d_in[2];
    const float* ew   = (const float*)d_in[3];
    float*       out  = (float*)d_out;

    float* hbuf;
    cudaGetSymbolAddress((void**)&hbuf, g_h);
    float* hA = hbuf;
    float* hB = hbuf + (size_t)N_NODES * D_FEAT;

    const int TB = 256;
    const int nodeBlocks = (N_NODES + TB - 1) / TB;
    const int edgeBlocks = (N_EDGES + TB - 1) / TB;
    const int spmmBlocks = (N_NODES * 32 + TB - 1) / TB;

    // CSR build (per launch; amortized over 10 SpMM iterations)
    k_zero_counts<<<nodeBlocks, TB>>>();
    k_hist<<<edgeBlocks, TB>>>(erow);
    k_scan<<<1, 1024>>>();
    k_scatter<<<edgeBlocks, TB>>>(erow, ecol, ew);

    // 10 propagation steps; iter 0 reads x directly, iter 9 writes d_out.
    const float* src = x;
    for (int k = 0; k < K_STEPS; k++) {
        float* dst = (k == K_STEPS - 1) ? out : ((k & 1) ? hB : hA);
        k_spmm<<<spmmBlocks, TB>>>(src, x, dst);
        src = dst;
    }
}

// round 3
// speedup vs baseline: 1.0008x; 1.0008x over previous
#include <cuda_runtime.h>
#include <cstdint>

// APPNP: h <- 0.9 * A@h + 0.1 * x, 10 iterations, A given as edge list.
// Strategy: build CSR (grouped by destination row) once per launch, then run
// atomic-free warp-per-row SpMM 10x with register accumulators. Gathers of
// h[col] (25.6MB working set) hit L2.

#define N_NODES 100000
#define N_EDGES 3200000
#define D_FEAT  64
#define ALPHA   0.1f
#define K_STEPS 10

// -------- static device scratch (no allocations allowed) --------
__device__ int   g_count[N_NODES];
__device__ int   g_fill[N_NODES];
__device__ int   g_rowptr[N_NODES + 1];
__device__ int2  g_cw[N_EDGES];                     // {col, bits(weight)}
__device__ float g_h[2][(size_t)N_NODES * D_FEAT];  // ping-pong h buffers

// -------- CSR build --------
__global__ void k_zero_counts() {
    int i = blockIdx.x * blockDim.x + threadIdx.x;
    if (i < N_NODES) { g_count[i] = 0; g_fill[i] = 0; }
}

__global__ void k_hist(const int* __restrict__ erow) {
    int e = blockIdx.x * blockDim.x + threadIdx.x;
    if (e < N_EDGES) atomicAdd(&g_count[erow[e]], 1);
}

// single-block exclusive scan over g_count -> g_rowptr (n = N_NODES)
__global__ void k_scan() {
    __shared__ int sdata[1024];
    __shared__ int carry;
    if (threadIdx.x == 0) carry = 0;
    __syncthreads();
    for (int base = 0; base < N_NODES; base += 1024) {
        int i = base + threadIdx.x;
        int v = (i < N_NODES) ? g_count[i] : 0;
        sdata[threadIdx.x] = v;
        __syncthreads();
        // inclusive scan in shared
        for (int off = 1; off < 1024; off <<= 1) {
            int t = (threadIdx.x >= off) ? sdata[threadIdx.x - off] : 0;
            __syncthreads();
            sdata[threadIdx.x] += t;
            __syncthreads();
        }
        int incl = sdata[threadIdx.x];
        if (i < N_NODES) g_rowptr[i] = carry + incl - v;  // exclusive
        __syncthreads();
        if (threadIdx.x == 1023) carry += sdata[1023];
        __syncthreads();
    }
    if (threadIdx.x == 0) g_rowptr[N_NODES] = carry;
}

__global__ void k_scatter(const int* __restrict__ erow,
                          const int* __restrict__ ecol,
                          const float* __restrict__ ew) {
    int e = blockIdx.x * blockDim.x + threadIdx.x;
    if (e < N_EDGES) {
        int r = erow[e];
        int p = g_rowptr[r] + atomicAdd(&g_fill[r], 1);
        g_cw[p] = make_int2(ecol[e], __float_as_int(ew[e]));
    }
}

// -------- SpMM: one warp per row, float2 per lane (32 lanes * 2 = 64 feats) --------
__global__ void __launch_bounds__(256)
k_spmm(const float* __restrict__ src, const float* __restrict__ x,
       float* __restrict__ dst) {
    int warp = (blockIdx.x * blockDim.x + threadIdx.x) >> 5;
    int lane = threadIdx.x & 31;
    if (warp >= N_NODES) return;

    int beg = g_rowptr[warp];
    int end = g_rowptr[warp + 1];

    float accx = 0.0f, accy = 0.0f;

    for (int base = beg; base < end; base += 32) {
        int e = base + lane;
        int2 cw = (e < end) ? g_cw[e] : make_int2(0, 0);
        int m = end - base; if (m > 32) m = 32;
        #pragma unroll 4
        for (int j = 0; j < m; j++) {
            int   c  = __shfl_sync(0xffffffffu, cw.x, j);
            float wv = __int_as_float(__shfl_sync(0xffffffffu, cw.y, j));
            float2 hv = *(const float2*)(src + (size_t)c * D_FEAT + lane * 2);
            accx = fmaf(wv, hv.x, accx);
            accy = fmaf(wv, hv.y, accy);
        }
    }

    float2 xv = *(const float2*)(x + (size_t)warp * D_FEAT + lane * 2);
    float2 out;
    out.x = fmaf(1.0f - ALPHA, accx, ALPHA * xv.x);
    out.y = fmaf(1.0f - ALPHA, accy, ALPHA * xv.y);
    *(float2*)(dst + (size_t)warp * D_FEAT + lane * 2) = out;
}

extern "C" void kernel_launch(void* const* d_in, const int* in_sizes, int n_in,
                              void* d_out, int out_size) {
    const float* x    = (const float*)d_in[0];
    const int*   erow = (const int*)d_in[1];
    const int*   ecol = (const int*)d_in[2];
    const float* ew   = (const float*)d_in[3];
    float*       out  = (float*)d_out;

    float* hbuf;
    cudaGetSymbolAddress((void**)&hbuf, g_h);
    float* hA = hbuf;
    float* hB = hbuf + (size_t)N_NODES * D_FEAT;

    const int TB = 256;
    const int nodeBlocks = (N_NODES + TB - 1) / TB;
    const int edgeBlocks = (N_EDGES + TB - 1) / TB;
    const int spmmBlocks = (N_NODES * 32 + TB - 1) / TB;

    // CSR build (per launch; amortized over 10 SpMM iterations)
    k_zero_counts<<<nodeBlocks, TB>>>();
    k_hist<<<edgeBlocks, TB>>>(erow);
    k_scan<<<1, 1024>>>();
    k_scatter<<<edgeBlocks, TB>>>(erow, ecol, ew);

    // 10 propagation steps; iter 0 reads x directly, iter 9 writes d_out.
    const float* src = x;
    for (int k = 0; k < K_STEPS; k++) {
        float* dst = (k == K_STEPS - 1) ? out : ((k & 1) ? hB : hA);
        k_spmm<<<spmmBlocks, TB>>>(src, x, dst);
        src = dst;
    }
}

// round 4
// speedup vs baseline: 1.1942x; 1.1932x over previous
#include <cuda_runtime.h>
#include <cstdint>

// APPNP: h <- 0.9 * A@h + 0.1 * x, 10 iterations, A given as edge list.
// CSR build (memset + int4-hist + 3-kernel hierarchical scan + scatter with
// atomicSub fill), then 10x atomic-free SpMM: one warp per destination row,
// two 16-lane halves each processing separate edges with float4 (LDG.128)
// gathers of h[col] out of L2. Edge weights pre-scaled by (1-alpha).

#define N_NODES 100000
#define N_EDGES 3200000
#define D_FEAT  64
#define ALPHA   0.1f
#define K_STEPS 10
#define SCAN_BLK 1024
#define N_SCAN_BLKS ((N_NODES + SCAN_BLK - 1) / SCAN_BLK)   // 98

// -------- static device scratch (no allocations allowed) --------
__device__ int   g_count[N_NODES];          // hist counts; consumed by scatter
__device__ int   g_rowptr[N_NODES + 1];
__device__ int   g_bsum[N_SCAN_BLKS];
__device__ int   g_boff[N_SCAN_BLKS];
__device__ int2  g_cw[N_EDGES];             // {col, bits(0.9*weight)}
__device__ float g_h[2][(size_t)N_NODES * D_FEAT];  // ping-pong h buffers

// -------- CSR build --------
__global__ void k_hist(const int4* __restrict__ erow4) {
    int t = blockIdx.x * blockDim.x + threadIdx.x;
    if (t < N_EDGES / 4) {
        int4 r = erow4[t];
        atomicAdd(&g_count[r.x], 1);
        atomicAdd(&g_count[r.y], 1);
        atomicAdd(&g_count[r.z], 1);
        atomicAdd(&g_count[r.w], 1);
    }
}

// per-block exclusive scan of g_count into g_rowptr + block totals
__global__ void __launch_bounds__(SCAN_BLK) k_scan1() {
    __shared__ int s[SCAN_BLK];
    int tid = threadIdx.x;
    int i = blockIdx.x * SCAN_BLK + tid;
    int v = (i < N_NODES) ? g_count[i] : 0;
    s[tid] = v;
    __syncthreads();
    #pragma unroll
    for (int off = 1; off < SCAN_BLK; off <<= 1) {
        int t = (tid >= off) ? s[tid - off] : 0;
        __syncthreads();
        s[tid] += t;
        __syncthreads();
    }
    if (i < N_NODES) g_rowptr[i] = s[tid] - v;  // exclusive within block
    if (tid == SCAN_BLK - 1) g_bsum[blockIdx.x] = s[tid];
}

// scan the 98 block totals
__global__ void k_scan2() {
    __shared__ int s[128];
    int tid = threadIdx.x;
    int v = (tid < N_SCAN_BLKS) ? g_bsum[tid] : 0;
    s[tid] = v;
    __syncthreads();
    #pragma unroll
    for (int off = 1; off < 128; off <<= 1) {
        int t = (tid >= off) ? s[tid - off] : 0;
        __syncthreads();
        s[tid] += t;
        __syncthreads();
    }
    if (tid < N_SCAN_BLKS) g_boff[tid] = s[tid] - v;
    if (tid == 0) g_rowptr[N_NODES] = N_EDGES;
}

__global__ void k_scan3() {
    int i = blockIdx.x * blockDim.x + threadIdx.x;
    if (i < N_NODES) g_rowptr[i] += g_boff[i >> 10];
}

__global__ void k_scatter(const int* __restrict__ erow,
                          const int* __restrict__ ecol,
                          const float* __restrict__ ew) {
    int e = blockIdx.x * blockDim.x + threadIdx.x;
    if (e < N_EDGES) {
        int r = erow[e];
        int p = g_rowptr[r] + atomicSub(&g_count[r], 1) - 1;
        g_cw[p] = make_int2(ecol[e], __float_as_int((1.0f - ALPHA) * ew[e]));
    }
}

// -------- SpMM: warp per row; two 16-lane halves, float4 per lane --------
__global__ void __launch_bounds__(256)
k_spmm(const float* __restrict__ src, const float* __restrict__ x,
       float* __restrict__ dst) {
    int warp = (blockIdx.x * blockDim.x + threadIdx.x) >> 5;
    int lane = threadIdx.x & 31;
    if (warp >= N_NODES) return;

    int beg = g_rowptr[warp];
    int end = g_rowptr[warp + 1];

    int half = lane >> 4;   // which half-warp
    int sub  = lane & 15;   // 4-feature group: feats sub*4 .. sub*4+3

    float4 acc = make_float4(0.f, 0.f, 0.f, 0.f);
    const float4* __restrict__ srcv = (const float4*)src;

    for (int base = beg; base < end; base += 32) {
        int e = base + lane;
        int2 cw = (e < end) ? g_cw[e] : make_int2(0, 0);
        int m = end - base; if (m > 32) m = 32;
        int steps = (m + 1) >> 1;          // halves interleave edges 2j+half
        #pragma unroll 4
        for (int j = 0; j < steps; j++) {
            int srcl = 2 * j + half;
            int   c  = __shfl_sync(0xffffffffu, cw.x, srcl);
            float wv = __int_as_float(__shfl_sync(0xffffffffu, cw.y, srcl));
            if (srcl < m) {
                float4 hv = srcv[c * 16 + sub];
                acc.x = fmaf(wv, hv.x, acc.x);
                acc.y = fmaf(wv, hv.y, acc.y);
                acc.z = fmaf(wv, hv.z, acc.z);
                acc.w = fmaf(wv, hv.w, acc.w);
            }
        }
    }

    // combine the two halves (each lane ends with the full sum for its feats)
    acc.x += __shfl_xor_sync(0xffffffffu, acc.x, 16);
    acc.y += __shfl_xor_sync(0xffffffffu, acc.y, 16);
    acc.z += __shfl_xor_sync(0xffffffffu, acc.z, 16);
    acc.w += __shfl_xor_sync(0xffffffffu, acc.w, 16);

    if (half == 0) {
        float4 xv = ((const float4*)x)[warp * 16 + sub];
        float4 o;
        o.x = fmaf(ALPHA, xv.x, acc.x);   // weights already carry (1-alpha)
        o.y = fmaf(ALPHA, xv.y, acc.y);
        o.z = fmaf(ALPHA, xv.z, acc.z);
        o.w = fmaf(ALPHA, xv.w, acc.w);
        ((float4*)dst)[warp * 16 + sub] = o;
    }
}

extern "C" void kernel_launch(void* const* d_in, const int* in_sizes, int n_in,
                              void* d_out, int out_size) {
    const float* x    = (const float*)d_in[0];
    const int*   erow = (const int*)d_in[1];
    const int*   ecol = (const int*)d_in[2];
    const float* ew   = (const float*)d_in[3];
    float*       out  = (float*)d_out;

    float* hbuf;
    cudaGetSymbolAddress((void**)&hbuf, g_h);
    float* hA = hbuf;
    float* hB = hbuf + (size_t)N_NODES * D_FEAT;
    int* countPtr;
    cudaGetSymbolAddress((void**)&countPtr, g_count);

    const int TB = 256;
    const int nodeBlocks = (N_NODES + TB - 1) / TB;
    const int edgeBlocks = (N_EDGES + TB - 1) / TB;
    const int histBlocks = (N_EDGES / 4 + TB - 1) / TB;
    const int spmmBlocks = (N_NODES * 32 + TB - 1) / TB;

    // CSR build (per launch; amortized over 10 SpMM iterations)
    cudaMemsetAsync(countPtr, 0, N_NODES * sizeof(int));
    k_hist<<<histBlocks, TB>>>((const int4*)erow);
    k_scan1<<<N_SCAN_BLKS, SCAN_BLK>>>();
    k_scan2<<<1, 128>>>();
    k_scan3<<<nodeBlocks, TB>>>();
    k_scatter<<<edgeBlocks, TB>>>(erow, ecol, ew);

    // 10 propagation steps; iter 0 reads x directly, iter 9 writes d_out.
    const float* src = x;
    for (int k = 0; k < K_STEPS; k++) {
        float* dst = (k == K_STEPS - 1) ? out : ((k & 1) ? hB : hA);
        k_spmm<<<spmmBlocks, TB>>>(src, x, dst);
        src = dst;
    }
}